// round 1
// baseline (speedup 1.0000x reference)
#include <cuda_runtime.h>

#define BATCH 32
#define SEQ   2048
#define EDIM  1024

// ---------------- scratch (no allocations allowed) ----------------
__device__ float g_qb[BATCH * EDIM];      // dec@W2 + b2 + b1
__device__ float g_scores[BATCH * SEQ];   // pre-softmax scores (bv dropped: softmax-invariant)
__device__ float g_attn[BATCH * SEQ];     // softmax weights

// ---------------- f32x2 packed-FMA helpers (sm_103a) ----------------
__device__ __forceinline__ unsigned long long pk2(float lo, float hi) {
    unsigned long long r;
    asm("mov.b64 %0, {%1, %2};" : "=l"(r) : "f"(lo), "f"(hi));
    return r;
}
__device__ __forceinline__ void upk2(unsigned long long p, float& lo, float& hi) {
    asm("mov.b64 {%0, %1}, %2;" : "=f"(lo), "=f"(hi) : "l"(p));
}
__device__ __forceinline__ void fma2(unsigned long long& d,
                                     unsigned long long a,
                                     unsigned long long b) {
    asm("fma.rn.f32x2 %0, %1, %2, %3;" : "=l"(d) : "l"(a), "l"(b), "l"(d));
}

// ---------------- K1: qb[b][e] = sum_d dec[b][d]*W2[d][e] + b2[e] + b1[e] ----------------
__global__ void qproj_kernel(const float* __restrict__ dec,
                             const float* __restrict__ w2,
                             const float* __restrict__ b2,
                             const float* __restrict__ b1) {
    __shared__ float sdec[EDIM];
    int b = blockIdx.x;
    int e = blockIdx.y * blockDim.x + threadIdx.x;
    for (int i = threadIdx.x; i < EDIM; i += blockDim.x)
        sdec[i] = dec[b * EDIM + i];
    __syncthreads();
    float acc = 0.f;
#pragma unroll 8
    for (int d = 0; d < EDIM; d++)
        acc += sdec[d] * w2[d * EDIM + e];
    g_qb[b * EDIM + e] = acc + b2[e] + b1[e];
}

// ---------------- K2: fused scores GEMM ----------------
// scores[b][s] = sum_n v[n] * tanh( (enc[b][s] . W1[:,n]) + qb[b][n] )
#define BM 128
#define BN 128
#define BK 16

__global__ __launch_bounds__(256, 2) void scores_kernel(
    const float* __restrict__ enc,
    const float* __restrict__ w1,
    const float* __restrict__ v) {
    __shared__ float As[BK][BM];     // A transposed: As[k][m]
    __shared__ float Bs[BK][BN];     // Bs[k][n]
    __shared__ float s_v[BN];
    __shared__ float s_q[BN];
    __shared__ float s_sum[BM];

    const int b    = blockIdx.y;
    const int row0 = blockIdx.x * BM;
    const int tid  = threadIdx.x;
    const int tx   = tid & 15;       // 0..15 -> n direction
    const int ty   = tid >> 4;       // 0..15 -> m direction

    const float* A = enc + (size_t)b * SEQ * EDIM + (size_t)row0 * EDIM;

    for (int i = tid; i < BM; i += 256) s_sum[i] = 0.f;

    for (int nc = 0; nc < EDIM / BN; nc++) {
        const int n0 = nc * BN;
        __syncthreads();                 // prior epilogue done before s_v/s_q rewrite
        if (tid < BN) {
            s_v[tid] = v[n0 + tid];
            s_q[tid] = g_qb[b * EDIM + n0 + tid];
        }

        unsigned long long acc[8][4];    // 8 rows x 4 col-pairs (8 cols)
#pragma unroll
        for (int i = 0; i < 8; i++)
#pragma unroll
            for (int j = 0; j < 4; j++) acc[i][j] = 0ull;

        for (int k0 = 0; k0 < EDIM; k0 += BK) {
            __syncthreads();
            // A tile: 128 rows x 16 k, transposed into As[k][m]
            {
                int t = tid;
#pragma unroll
                for (int r = 0; r < 2; r++, t += 256) {
                    int m  = t >> 2;          // 0..127
                    int k4 = (t & 3) * 4;     // 0,4,8,12
                    float4 val = *reinterpret_cast<const float4*>(
                        &A[(size_t)m * EDIM + k0 + k4]);
                    As[k4 + 0][m] = val.x;
                    As[k4 + 1][m] = val.y;
                    As[k4 + 2][m] = val.z;
                    As[k4 + 3][m] = val.w;
                }
            }
            // B tile: 16 k x 128 n
            {
                int t = tid;
#pragma unroll
                for (int r = 0; r < 2; r++, t += 256) {
                    int k  = t >> 5;          // 0..15
                    int n4 = (t & 31) * 4;    // 0..124
                    *reinterpret_cast<float4*>(&Bs[k][n4]) =
                        *reinterpret_cast<const float4*>(
                            &w1[(size_t)(k0 + k) * EDIM + n0 + n4]);
                }
            }
            __syncthreads();
#pragma unroll
            for (int k = 0; k < BK; k++) {
                float4 a0 = *reinterpret_cast<const float4*>(&As[k][ty * 8]);
                float4 a1 = *reinterpret_cast<const float4*>(&As[k][ty * 8 + 4]);
                float4 c0 = *reinterpret_cast<const float4*>(&Bs[k][tx * 8]);
                float4 c1 = *reinterpret_cast<const float4*>(&Bs[k][tx * 8 + 4]);
                unsigned long long bp0 = pk2(c0.x, c0.y);
                unsigned long long bp1 = pk2(c0.z, c0.w);
                unsigned long long bp2 = pk2(c1.x, c1.y);
                unsigned long long bp3 = pk2(c1.z, c1.w);
                float av[8] = {a0.x, a0.y, a0.z, a0.w, a1.x, a1.y, a1.z, a1.w};
#pragma unroll
                for (int i = 0; i < 8; i++) {
                    unsigned long long ap = pk2(av[i], av[i]);
                    fma2(acc[i][0], ap, bp0);
                    fma2(acc[i][1], ap, bp1);
                    fma2(acc[i][2], ap, bp2);
                    fma2(acc[i][3], ap, bp3);
                }
            }
        }

        // epilogue: tanh(acc + q) . v, reduce over this n-chunk
#pragma unroll
        for (int i = 0; i < 8; i++) {
            float partial = 0.f;
#pragma unroll
            for (int j = 0; j < 4; j++) {
                float lo, hi;
                upk2(acc[i][j], lo, hi);
                int n = tx * 8 + 2 * j;
                partial += tanhf(lo + s_q[n])     * s_v[n];
                partial += tanhf(hi + s_q[n + 1]) * s_v[n + 1];
            }
            // reduce across the 16 tx lanes (each 16-lane warp half = distinct rows)
            partial += __shfl_xor_sync(0xffffffffu, partial, 1);
            partial += __shfl_xor_sync(0xffffffffu, partial, 2);
            partial += __shfl_xor_sync(0xffffffffu, partial, 4);
            partial += __shfl_xor_sync(0xffffffffu, partial, 8);
            if (tx == 0) atomicAdd(&s_sum[ty * 8 + i], partial);
        }
    }
    __syncthreads();
    for (int i = tid; i < BM; i += 256)
        g_scores[b * SEQ + row0 + i] = s_sum[i];
}

// ---------------- K3: softmax over S per batch ----------------
__global__ void softmax_kernel() {
    const int b   = blockIdx.x;
    const int tid = threadIdx.x;            // 256 threads
    const int lane = tid & 31, wid = tid >> 5;
    __shared__ float red[8];
    __shared__ float bcast;

    float vals[SEQ / 256];
#pragma unroll
    for (int i = 0; i < SEQ / 256; i++)
        vals[i] = g_scores[b * SEQ + i * 256 + tid];

    float m = vals[0];
#pragma unroll
    for (int i = 1; i < SEQ / 256; i++) m = fmaxf(m, vals[i]);
#pragma unroll
    for (int off = 16; off >= 1; off >>= 1)
        m = fmaxf(m, __shfl_xor_sync(0xffffffffu, m, off));
    if (lane == 0) red[wid] = m;
    __syncthreads();
    float bm = red[0];
#pragma unroll
    for (int w = 1; w < 8; w++) bm = fmaxf(bm, red[w]);
    __syncthreads();

    float sum = 0.f;
#pragma unroll
    for (int i = 0; i < SEQ / 256; i++) {
        vals[i] = __expf(vals[i] - bm);
        sum += vals[i];
    }
#pragma unroll
    for (int off = 16; off >= 1; off >>= 1)
        sum += __shfl_xor_sync(0xffffffffu, sum, off);
    if (lane == 0) red[wid] = sum;
    __syncthreads();
    if (tid == 0) {
        float t = 0.f;
#pragma unroll
        for (int w = 0; w < 8; w++) t += red[w];
        bcast = 1.0f / t;
    }
    __syncthreads();
    float inv = bcast;
#pragma unroll
    for (int i = 0; i < SEQ / 256; i++)
        g_attn[b * SEQ + i * 256 + tid] = vals[i] * inv;
}

// ---------------- K4: context[b][e] = sum_s attn[b][s] * enc[b][s][e] ----------------
__global__ void context_kernel(const float* __restrict__ enc,
                               float* __restrict__ out) {
    const int b = blockIdx.y;
    const int e = blockIdx.x * blockDim.x + threadIdx.x;
    const float* A  = enc + (size_t)b * SEQ * EDIM;
    const float* at = g_attn + b * SEQ;
    float acc = 0.f;
#pragma unroll 8
    for (int s = 0; s < SEQ; s++)
        acc = fmaf(at[s], A[(size_t)s * EDIM + e], acc);
    out[b * EDIM + e] = acc;
}

// ---------------- launch ----------------
extern "C" void kernel_launch(void* const* d_in, const int* in_sizes, int n_in,
                              void* d_out, int out_size) {
    const float* enc = (const float*)d_in[0];
    const float* dec = (const float*)d_in[1];
    const float* w1  = (const float*)d_in[2];
    const float* b1  = (const float*)d_in[3];
    const float* w2  = (const float*)d_in[4];
    const float* b2  = (const float*)d_in[5];
    const float* v   = (const float*)d_in[6];
    // d_in[7] = bv: constant shift on scores -> softmax-invariant -> unused
    float* out = (float*)d_out;

    qproj_kernel<<<dim3(BATCH, EDIM / 256), 256>>>(dec, w2, b2, b1);
    scores_kernel<<<dim3(SEQ / BM, BATCH), 256>>>(enc, w1, v);
    softmax_kernel<<<BATCH, 256>>>();
    context_kernel<<<dim3(EDIM / 128, BATCH), 128>>>(enc, out);
}

// round 5
// speedup vs baseline: 2.7347x; 2.7347x over previous
#include <cuda_runtime.h>
#include <cuda_bf16.h>
#include <cstdint>

#define BATCH 32
#define SEQ   2048
#define EDIM  1024
#define MROWS (BATCH * SEQ)   // 65536

// ---------------- device scratch (no allocations allowed) ----------------
__device__ float g_qb[BATCH * EDIM];
__device__ float g_scores[BATCH * SEQ];
__device__ float g_attn[BATCH * SEQ];
__device__ float g_ctx_part[8 * BATCH * EDIM];
__device__ __nv_bfloat16 g_a_hi[(size_t)MROWS * EDIM];  // 128 MB
__device__ __nv_bfloat16 g_a_lo[(size_t)MROWS * EDIM];  // 128 MB
__device__ __nv_bfloat16 g_b_hi[EDIM * EDIM];           // W1^T hi  [n][k]
__device__ __nv_bfloat16 g_b_lo[EDIM * EDIM];           // W1^T lo  [n][k]

// ---------------- PTX helpers (all sm_80-compatible) ----------------
__device__ __forceinline__ uint32_t smem_u32(const void* p) {
    uint32_t a;
    asm("{ .reg .u64 t; cvta.to.shared.u64 t, %1; cvt.u32.u64 %0, t; }" : "=r"(a) : "l"(p));
    return a;
}
__device__ __forceinline__ void ldsm_x4(uint32_t* r, uint32_t addr) {
    asm volatile("ldmatrix.sync.aligned.m8n8.x4.shared.b16 {%0,%1,%2,%3}, [%4];"
                 : "=r"(r[0]), "=r"(r[1]), "=r"(r[2]), "=r"(r[3]) : "r"(addr));
}
__device__ __forceinline__ void mma_bf16(float* c, const uint32_t* a, const uint32_t* b) {
    asm volatile(
        "mma.sync.aligned.m16n8k16.row.col.f32.bf16.bf16.f32 "
        "{%0,%1,%2,%3}, {%4,%5,%6,%7}, {%8,%9}, {%0,%1,%2,%3};"
        : "+f"(c[0]), "+f"(c[1]), "+f"(c[2]), "+f"(c[3])
        : "r"(a[0]), "r"(a[1]), "r"(a[2]), "r"(a[3]), "r"(b[0]), "r"(b[1]));
}
__device__ __forceinline__ void cp16(uint32_t s, const void* g) {
    asm volatile("cp.async.cg.shared.global [%0], [%1], 16;" :: "r"(s), "l"(g));
}
#define CP_COMMIT() asm volatile("cp.async.commit_group;" ::: "memory")
#define CP_WAIT1()  asm volatile("cp.async.wait_group 1;" ::: "memory")

__device__ __forceinline__ float fast_tanh(float x) {
    float e = __expf(2.0f * x);
    return 1.0f - 2.0f / (e + 1.0f);
}

// ---------------- K0a: split enc into bf16 hi/lo ----------------
__global__ void split_enc_kernel(const float* __restrict__ enc) {
    size_t base = ((size_t)blockIdx.x * 256 + threadIdx.x) * 8;
    float4 v0 = *reinterpret_cast<const float4*>(enc + base);
    float4 v1 = *reinterpret_cast<const float4*>(enc + base + 4);
    float x[8] = {v0.x, v0.y, v0.z, v0.w, v1.x, v1.y, v1.z, v1.w};
    __nv_bfloat162 h[4], l[4];
#pragma unroll
    for (int i = 0; i < 4; i++) {
        __nv_bfloat16 h0 = __float2bfloat16(x[2 * i]);
        __nv_bfloat16 h1 = __float2bfloat16(x[2 * i + 1]);
        h[i] = __halves2bfloat162(h0, h1);
        l[i] = __halves2bfloat162(
            __float2bfloat16(x[2 * i] - __bfloat162float(h0)),
            __float2bfloat16(x[2 * i + 1] - __bfloat162float(h1)));
    }
    uint4 uh, ul;
    uh.x = reinterpret_cast<uint32_t&>(h[0]); uh.y = reinterpret_cast<uint32_t&>(h[1]);
    uh.z = reinterpret_cast<uint32_t&>(h[2]); uh.w = reinterpret_cast<uint32_t&>(h[3]);
    ul.x = reinterpret_cast<uint32_t&>(l[0]); ul.y = reinterpret_cast<uint32_t&>(l[1]);
    ul.z = reinterpret_cast<uint32_t&>(l[2]); ul.w = reinterpret_cast<uint32_t&>(l[3]);
    *reinterpret_cast<uint4*>(g_a_hi + base) = uh;
    *reinterpret_cast<uint4*>(g_a_lo + base) = ul;
}

// ---------------- K0b: transpose + split W1 -> B[n][k] ----------------
__global__ void split_w1t_kernel(const float* __restrict__ w1) {
    __shared__ float t[32][33];
    int k0 = blockIdx.x * 32, n0 = blockIdx.y * 32;
    int tx = threadIdx.x, ty = threadIdx.y;
    t[ty][tx] = w1[(k0 + ty) * EDIM + n0 + tx];
    __syncthreads();
    float x = t[tx][ty];  // = w1[k0+tx][n0+ty]
    __nv_bfloat16 hi = __float2bfloat16(x);
    __nv_bfloat16 lo = __float2bfloat16(x - __bfloat162float(hi));
    g_b_hi[(n0 + ty) * EDIM + k0 + tx] = hi;
    g_b_lo[(n0 + ty) * EDIM + k0 + tx] = lo;
}

// ---------------- K1: qb = dec@W2 + b2 + b1 ----------------
__global__ void qproj_kernel(const float* __restrict__ dec,
                             const float* __restrict__ w2,
                             const float* __restrict__ b2,
                             const float* __restrict__ b1) {
    __shared__ float sdec[EDIM];
    int b = blockIdx.x;
    int e = blockIdx.y * blockDim.x + threadIdx.x;
    for (int i = threadIdx.x; i < EDIM; i += blockDim.x)
        sdec[i] = dec[b * EDIM + i];
    __syncthreads();
    float acc = 0.f;
#pragma unroll 8
    for (int d = 0; d < EDIM; d++)
        acc += sdec[d] * w2[d * EDIM + e];
    g_qb[b * EDIM + e] = acc + b2[e] + b1[e];
}

// ---------------- K2: HMMA fused scores GEMM ----------------
// SMEM: 2 stages x { A_hi 8K | A_lo 8K | B_hi 8K | B_lo 8K }, then q/v/sc
#define STG_BYTES 32768
#define AHI_OFF 0
#define ALO_OFF 8192
#define BHI_OFF 16384
#define BLO_OFF 24576
#define QV_OFF  65536
#define SCORES_SMEM (QV_OFF + 3 * 512)   // 67072

// swizzled offset for row r, 16B-chunk kc (4 chunks per 64B row)
__device__ __forceinline__ uint32_t swz_off(int r, int kc) {
    return (uint32_t)(r * 64 + ((kc ^ ((r >> 1) & 3)) << 4));
}

__global__ __launch_bounds__(256, 2) void scores_mma_kernel(const float* __restrict__ v) {
    extern __shared__ char sm[];
    const uint32_t sb = smem_u32(sm);
    const int tid = threadIdx.x;
    const int lane = tid & 31, wid = tid >> 5;
    const int wy = wid >> 1, wn = wid & 1;       // 4 x 2 warp grid
    const int m0 = blockIdx.x * 128;
    const int b  = m0 >> 11;

    float* s_q  = reinterpret_cast<float*>(sm + QV_OFF);
    float* s_v  = s_q + 128;
    float* s_sc = s_v + 128;

    // ldmatrix per-lane invariants
    // A (row-major m x k): lane -> m offset + k-chunk
    const int a_mi = (lane & 7) + ((lane >> 3) & 1) * 8;
    const int a_kc = lane >> 4;                   // 0/1 (8-elem units)
    int a_row[2], a_swz[2];
#pragma unroll
    for (int mt = 0; mt < 2; mt++) {
        int r = wy * 32 + mt * 16 + a_mi;
        a_row[mt] = r * 64;
        a_swz[mt] = (r >> 1) & 3;
    }
    // B ([n][k] row-major = col-major KxN): lane -> n offset + k-chunk
    const int b_ni = (lane & 7) + ((lane >> 4) & 1) * 8;
    const int b_kc = (lane >> 3) & 1;
    int b_row[4], b_swz[4];
#pragma unroll
    for (int p = 0; p < 4; p++) {
        int n = wn * 64 + p * 16 + b_ni;
        b_row[p] = n * 64;
        b_swz[p] = (n >> 1) & 3;
    }

    if (tid < 128) s_sc[tid] = 0.f;

    for (int np = 0; np < 8; np++) {
        const int n0 = np * 128;
        if (tid < 128) {
            s_q[tid] = g_qb[b * EDIM + n0 + tid];
            s_v[tid] = v[n0 + tid];
        }

        float acc[2][8][4];
#pragma unroll
        for (int mt = 0; mt < 2; mt++)
#pragma unroll
            for (int nt = 0; nt < 8; nt++)
#pragma unroll
                for (int r = 0; r < 4; r++) acc[mt][nt][r] = 0.f;

        // cp.async stage loader
        auto load_stage = [&](int buf, int k0) {
            uint32_t base = sb + buf * STG_BYTES;
#pragma unroll
            for (int i = 0; i < 2; i++) {
                int c = tid + i * 256;
                int row = c >> 2, kc = c & 3;
                uint32_t so = swz_off(row, kc);
                size_t ga = (size_t)(m0 + row) * EDIM + k0 + kc * 8;
                size_t gb = (size_t)(n0 + row) * EDIM + k0 + kc * 8;
                cp16(base + AHI_OFF + so, g_a_hi + ga);
                cp16(base + ALO_OFF + so, g_a_lo + ga);
                cp16(base + BHI_OFF + so, g_b_hi + gb);
                cp16(base + BLO_OFF + so, g_b_lo + gb);
            }
        };

        load_stage(0, 0);
        CP_COMMIT();

        for (int ks = 0; ks < 32; ks++) {
            __syncthreads();                       // guard buffer (ks+1)&1
            if (ks + 1 < 32) load_stage((ks + 1) & 1, (ks + 1) * 32);
            CP_COMMIT();
            CP_WAIT1();                            // stage ks resident
            __syncthreads();

            const uint32_t base = sb + (ks & 1) * STG_BYTES;
#pragma unroll
            for (int kk = 0; kk < 2; kk++) {
                uint32_t ah[2][4], al[2][4];
#pragma unroll
                for (int mt = 0; mt < 2; mt++) {
                    uint32_t ao = (uint32_t)(a_row[mt] +
                        (((kk * 2 + a_kc) ^ a_swz[mt]) << 4));
                    ldsm_x4(ah[mt], base + AHI_OFF + ao);
                    ldsm_x4(al[mt], base + ALO_OFF + ao);
                }
#pragma unroll
                for (int p = 0; p < 4; p++) {
                    uint32_t bo = (uint32_t)(b_row[p] +
                        (((kk * 2 + b_kc) ^ b_swz[p]) << 4));
                    uint32_t bh[4], bl[4];
                    ldsm_x4(bh, base + BHI_OFF + bo);
                    ldsm_x4(bl, base + BLO_OFF + bo);
#pragma unroll
                    for (int mt = 0; mt < 2; mt++) {
                        mma_bf16(acc[mt][2 * p],     ah[mt], bh);
                        mma_bf16(acc[mt][2 * p],     ah[mt], bl);
                        mma_bf16(acc[mt][2 * p],     al[mt], bh);
                        mma_bf16(acc[mt][2 * p + 1], ah[mt], bh + 2);
                        mma_bf16(acc[mt][2 * p + 1], ah[mt], bl + 2);
                        mma_bf16(acc[mt][2 * p + 1], al[mt], bh + 2);
                    }
                }
            }
        }

        // epilogue: tanh(acc + q) . v   (rows: wy*32 + mt*16 + lane>>2 (+8))
        float part[4] = {0.f, 0.f, 0.f, 0.f};
#pragma unroll
        for (int mt = 0; mt < 2; mt++)
#pragma unroll
            for (int nt = 0; nt < 8; nt++) {
                int qi = wn * 64 + nt * 8 + 2 * (lane & 3);
                float* c = acc[mt][nt];
                part[mt * 2 + 0] += fast_tanh(c[0] + s_q[qi]) * s_v[qi]
                                  + fast_tanh(c[1] + s_q[qi + 1]) * s_v[qi + 1];
                part[mt * 2 + 1] += fast_tanh(c[2] + s_q[qi]) * s_v[qi]
                                  + fast_tanh(c[3] + s_q[qi + 1]) * s_v[qi + 1];
            }
#pragma unroll
        for (int i = 0; i < 4; i++) {
            part[i] += __shfl_xor_sync(0xffffffffu, part[i], 1);
            part[i] += __shfl_xor_sync(0xffffffffu, part[i], 2);
        }
        if ((lane & 3) == 0) {
            int rbase = wy * 32 + (lane >> 2);
            atomicAdd(&s_sc[rbase],          part[0]);
            atomicAdd(&s_sc[rbase + 8],      part[1]);
            atomicAdd(&s_sc[rbase + 16],     part[2]);
            atomicAdd(&s_sc[rbase + 24],     part[3]);
        }
        __syncthreads();   // s_sc/s_q stable before next pass
    }

    if (tid < 128) g_scores[m0 + tid] = s_sc[tid];
}

// ---------------- K3: softmax over S per batch ----------------
__global__ void softmax_kernel() {
    const int b = blockIdx.x;
    const int tid = threadIdx.x;
    const int lane = tid & 31, wid = tid >> 5;
    __shared__ float red[8];
    __shared__ float bcast;

    float vals[SEQ / 256];
#pragma unroll
    for (int i = 0; i < SEQ / 256; i++)
        vals[i] = g_scores[b * SEQ + i * 256 + tid];

    float m = vals[0];
#pragma unroll
    for (int i = 1; i < SEQ / 256; i++) m = fmaxf(m, vals[i]);
#pragma unroll
    for (int off = 16; off >= 1; off >>= 1)
        m = fmaxf(m, __shfl_xor_sync(0xffffffffu, m, off));
    if (lane == 0) red[wid] = m;
    __syncthreads();
    float bm = red[0];
#pragma unroll
    for (int w = 1; w < 8; w++) bm = fmaxf(bm, red[w]);
    __syncthreads();

    float sum = 0.f;
#pragma unroll
    for (int i = 0; i < SEQ / 256; i++) {
        vals[i] = __expf(vals[i] - bm);
        sum += vals[i];
    }
#pragma unroll
    for (int off = 16; off >= 1; off >>= 1)
        sum += __shfl_xor_sync(0xffffffffu, sum, off);
    if (lane == 0) red[wid] = sum;
    __syncthreads();
    if (tid == 0) {
        float t = 0.f;
#pragma unroll
        for (int w = 0; w < 8; w++) t += red[w];
        bcast = 1.0f / t;
    }
    __syncthreads();
    float inv = bcast;
#pragma unroll
    for (int i = 0; i < SEQ / 256; i++)
        g_attn[b * SEQ + i * 256 + tid] = vals[i] * inv;
}

// ---------------- K4a: context partials (split-S) ----------------
__global__ void context_part_kernel(const float* __restrict__ enc) {
    const int b = blockIdx.z;
    const int sc = blockIdx.y;
    const int e = blockIdx.x * 128 + threadIdx.x;
    const float* A  = enc + (size_t)b * SEQ * EDIM + (size_t)sc * 256 * EDIM;
    const float* at = g_attn + b * SEQ + sc * 256;
    float acc = 0.f;
#pragma unroll 8
    for (int s = 0; s < 256; s++)
        acc = fmaf(at[s], A[(size_t)s * EDIM + e], acc);
    g_ctx_part[((size_t)sc * BATCH + b) * EDIM + e] = acc;
}

// ---------------- K4b: sum partials ----------------
__global__ void context_sum_kernel(float* __restrict__ out) {
    const int i = blockIdx.x * 256 + threadIdx.x;
    float a = 0.f;
#pragma unroll
    for (int sc = 0; sc < 8; sc++)
        a += g_ctx_part[(size_t)sc * BATCH * EDIM + i];
    out[i] = a;
}

// ---------------- launch ----------------
extern "C" void kernel_launch(void* const* d_in, const int* in_sizes, int n_in,
                              void* d_out, int out_size) {
    const float* enc = (const float*)d_in[0];
    const float* dec = (const float*)d_in[1];
    const float* w1  = (const float*)d_in[2];
    const float* b1  = (const float*)d_in[3];
    const float* w2  = (const float*)d_in[4];
    const float* b2  = (const float*)d_in[5];
    const float* v   = (const float*)d_in[6];
    // d_in[7] = bv: softmax-invariant, dropped
    float* out = (float*)d_out;

    cudaFuncSetAttribute(scores_mma_kernel,
                         cudaFuncAttributeMaxDynamicSharedMemorySize, SCORES_SMEM);

    split_enc_kernel<<<(size_t)MROWS * EDIM / 2048, 256>>>(enc);
    split_w1t_kernel<<<dim3(32, 32), dim3(32, 32)>>>(w1);
    qproj_kernel<<<dim3(BATCH, EDIM / 256), 256>>>(dec, w2, b2, b1);
    scores_mma_kernel<<<MROWS / 128, 256, SCORES_SMEM>>>(v);
    softmax_kernel<<<BATCH, 256>>>();
    context_part_kernel<<<dim3(EDIM / 128, 8, BATCH), 128>>>(enc);
    context_sum_kernel<<<BATCH * EDIM / 256, 256>>>(out);
}

// round 6
// speedup vs baseline: 5.7436x; 2.1003x over previous
#include <cuda_runtime.h>
#include <cuda_fp16.h>
#include <cstdint>

#define BATCH 32
#define SEQ   2048
#define EDIM  1024
#define MROWS (BATCH * SEQ)   // 65536
#define NSC   16              // context S-split chunks

// ---------------- device scratch (no allocations allowed) ----------------
__device__ float g_qb[BATCH * EDIM];
__device__ float g_scores[BATCH * SEQ];
__device__ float g_attn[BATCH * SEQ];
__device__ float g_ctx_part[NSC * BATCH * EDIM];
__device__ __half g_a[(size_t)MROWS * EDIM];   // enc, fp16 (128 MB)
__device__ __half g_b[EDIM * EDIM];            // W1^T, fp16 [n][k]

// ---------------- PTX helpers (sm_80-compatible) ----------------
__device__ __forceinline__ uint32_t smem_u32(const void* p) {
    uint32_t a;
    asm("{ .reg .u64 t; cvta.to.shared.u64 t, %1; cvt.u32.u64 %0, t; }" : "=r"(a) : "l"(p));
    return a;
}
__device__ __forceinline__ void ldsm_x4(uint32_t* r, uint32_t addr) {
    asm volatile("ldmatrix.sync.aligned.m8n8.x4.shared.b16 {%0,%1,%2,%3}, [%4];"
                 : "=r"(r[0]), "=r"(r[1]), "=r"(r[2]), "=r"(r[3]) : "r"(addr));
}
__device__ __forceinline__ void mma_fp16(float* c, const uint32_t* a, const uint32_t* b) {
    asm volatile(
        "mma.sync.aligned.m16n8k16.row.col.f32.f16.f16.f32 "
        "{%0,%1,%2,%3}, {%4,%5,%6,%7}, {%8,%9}, {%0,%1,%2,%3};"
        : "+f"(c[0]), "+f"(c[1]), "+f"(c[2]), "+f"(c[3])
        : "r"(a[0]), "r"(a[1]), "r"(a[2]), "r"(a[3]), "r"(b[0]), "r"(b[1]));
}
__device__ __forceinline__ void cp16(uint32_t s, const void* g) {
    asm volatile("cp.async.cg.shared.global [%0], [%1], 16;" :: "r"(s), "l"(g));
}
#define CP_COMMIT() asm volatile("cp.async.commit_group;" ::: "memory")
#define CP_WAIT1()  asm volatile("cp.async.wait_group 1;" ::: "memory")

__device__ __forceinline__ float fast_tanh(float x) {
    float e = __expf(2.0f * x);
    return 1.0f - 2.0f / (e + 1.0f);
}

// ---------------- K0a: convert enc -> fp16 ----------------
__global__ void conv_enc_kernel(const float* __restrict__ enc) {
    size_t base = ((size_t)blockIdx.x * 256 + threadIdx.x) * 8;
    float4 v0 = *reinterpret_cast<const float4*>(enc + base);
    float4 v1 = *reinterpret_cast<const float4*>(enc + base + 4);
    __half2 h[4];
    h[0] = __floats2half2_rn(v0.x, v0.y);
    h[1] = __floats2half2_rn(v0.z, v0.w);
    h[2] = __floats2half2_rn(v1.x, v1.y);
    h[3] = __floats2half2_rn(v1.z, v1.w);
    uint4 u;
    u.x = reinterpret_cast<uint32_t&>(h[0]); u.y = reinterpret_cast<uint32_t&>(h[1]);
    u.z = reinterpret_cast<uint32_t&>(h[2]); u.w = reinterpret_cast<uint32_t&>(h[3]);
    *reinterpret_cast<uint4*>(g_a + base) = u;
}

// ---------------- K0b: transpose + convert W1 -> B[n][k] fp16 ----------------
__global__ void conv_w1t_kernel(const float* __restrict__ w1) {
    __shared__ float t[32][33];
    int k0 = blockIdx.x * 32, n0 = blockIdx.y * 32;
    int tx = threadIdx.x, ty = threadIdx.y;
    t[ty][tx] = w1[(k0 + ty) * EDIM + n0 + tx];
    __syncthreads();
    g_b[(n0 + ty) * EDIM + k0 + tx] = __float2half_rn(t[tx][ty]);
}

// ---------------- K1: qb = dec@W2 + b2 + b1 ----------------
__global__ void qproj_kernel(const float* __restrict__ dec,
                             const float* __restrict__ w2,
                             const float* __restrict__ b2,
                             const float* __restrict__ b1) {
    __shared__ float sdec[EDIM];
    int b = blockIdx.x;
    int e = blockIdx.y * blockDim.x + threadIdx.x;
    for (int i = threadIdx.x; i < EDIM; i += blockDim.x)
        sdec[i] = dec[b * EDIM + i];
    __syncthreads();
    float acc = 0.f;
#pragma unroll 8
    for (int d = 0; d < EDIM; d++)
        acc += sdec[d] * w2[d * EDIM + e];
    g_qb[b * EDIM + e] = acc + b2[e] + b1[e];
}

// ---------------- K2: fp16 HMMA fused scores GEMM ----------------
// 2 stages x { A 16K | B 16K }  (BM=128, BN=128, BK=64)
#define STG_BYTES 32768
#define A_OFF 0
#define B_OFF 16384
#define QV_OFF  65536
#define SCORES_SMEM (QV_OFF + 3 * 512)   // 67072

// rows are 128B (64 halves), 8 chunks of 16B, full XOR swizzle
__device__ __forceinline__ uint32_t swz_off(int r, int kc) {
    return (uint32_t)(r * 128 + ((kc ^ (r & 7)) << 4));
}

__global__ __launch_bounds__(256, 2) void scores_mma_kernel(const float* __restrict__ v) {
    extern __shared__ char sm[];
    const uint32_t sb = smem_u32(sm);
    const int tid = threadIdx.x;
    const int lane = tid & 31, wid = tid >> 5;
    const int wy = wid >> 1, wn = wid & 1;       // 4 x 2 warp grid
    const int m0 = blockIdx.x * 128;
    const int b  = m0 >> 11;

    float* s_q  = reinterpret_cast<float*>(sm + QV_OFF);
    float* s_v  = s_q + 128;
    float* s_sc = s_v + 128;

    // ldmatrix lane invariants (mappings verified in R5)
    const int a_mi = (lane & 7) + ((lane >> 3) & 1) * 8;
    const int a_kc = lane >> 4;                   // 0/1
    int a_row[2], a_swz[2];
#pragma unroll
    for (int mt = 0; mt < 2; mt++) {
        int r = wy * 32 + mt * 16 + a_mi;
        a_row[mt] = r * 128;
        a_swz[mt] = r & 7;
    }
    const int b_ni = (lane & 7) + ((lane >> 4) & 1) * 8;
    const int b_kc = (lane >> 3) & 1;
    int b_row[4], b_swz[4];
#pragma unroll
    for (int p = 0; p < 4; p++) {
        int n = wn * 64 + p * 16 + b_ni;
        b_row[p] = n * 128;
        b_swz[p] = n & 7;
    }

    if (tid < 128) s_sc[tid] = 0.f;

    for (int np = 0; np < 8; np++) {
        const int n0 = np * 128;
        if (tid < 128) {
            s_q[tid] = g_qb[b * EDIM + n0 + tid];
            s_v[tid] = v[n0 + tid];
        }

        float acc[2][8][4];
#pragma unroll
        for (int mt = 0; mt < 2; mt++)
#pragma unroll
            for (int nt = 0; nt < 8; nt++)
#pragma unroll
                for (int r = 0; r < 4; r++) acc[mt][nt][r] = 0.f;

        auto load_stage = [&](int buf, int k0) {
            uint32_t base = sb + buf * STG_BYTES;
#pragma unroll
            for (int i = 0; i < 4; i++) {
                int c = tid + i * 256;           // 0..1023
                int row = c >> 3, kc = c & 7;
                uint32_t so = swz_off(row, kc);
                size_t ga = (size_t)(m0 + row) * EDIM + k0 + kc * 8;
                size_t gb = (size_t)(n0 + row) * EDIM + k0 + kc * 8;
                cp16(base + A_OFF + so, g_a + ga);
                cp16(base + B_OFF + so, g_b + gb);
            }
        };

        load_stage(0, 0);
        CP_COMMIT();

        for (int ks = 0; ks < 16; ks++) {
            __syncthreads();                       // all warps done with buf (ks+1)&1
            if (ks + 1 < 16) load_stage((ks + 1) & 1, (ks + 1) * 64);
            CP_COMMIT();
            CP_WAIT1();                            // stage ks resident
            __syncthreads();

            const uint32_t base = sb + (ks & 1) * STG_BYTES;
#pragma unroll
            for (int kk = 0; kk < 4; kk++) {       // 4 x k16 within k64 stage
                uint32_t af[2][4];
#pragma unroll
                for (int mt = 0; mt < 2; mt++) {
                    uint32_t ao = (uint32_t)(a_row[mt] +
                        (((kk * 2 + a_kc) ^ a_swz[mt]) << 4));
                    ldsm_x4(af[mt], base + A_OFF + ao);
                }
#pragma unroll
                for (int p = 0; p < 4; p++) {
                    uint32_t bo = (uint32_t)(b_row[p] +
                        (((kk * 2 + b_kc) ^ b_swz[p]) << 4));
                    uint32_t bf[4];
                    ldsm_x4(bf, base + B_OFF + bo);
#pragma unroll
                    for (int mt = 0; mt < 2; mt++) {
                        mma_fp16(acc[mt][2 * p],     af[mt], bf);
                        mma_fp16(acc[mt][2 * p + 1], af[mt], bf + 2);
                    }
                }
            }
        }

        // epilogue: tanh(acc + q) . v
        float part[4] = {0.f, 0.f, 0.f, 0.f};
#pragma unroll
        for (int mt = 0; mt < 2; mt++)
#pragma unroll
            for (int nt = 0; nt < 8; nt++) {
                int qi = wn * 64 + nt * 8 + 2 * (lane & 3);
                float* c = acc[mt][nt];
                part[mt * 2 + 0] += fast_tanh(c[0] + s_q[qi]) * s_v[qi]
                                  + fast_tanh(c[1] + s_q[qi + 1]) * s_v[qi + 1];
                part[mt * 2 + 1] += fast_tanh(c[2] + s_q[qi]) * s_v[qi]
                                  + fast_tanh(c[3] + s_q[qi + 1]) * s_v[qi + 1];
            }
#pragma unroll
        for (int i = 0; i < 4; i++) {
            part[i] += __shfl_xor_sync(0xffffffffu, part[i], 1);
            part[i] += __shfl_xor_sync(0xffffffffu, part[i], 2);
        }
        if ((lane & 3) == 0) {
            int rbase = wy * 32 + (lane >> 2);
            atomicAdd(&s_sc[rbase],      part[0]);
            atomicAdd(&s_sc[rbase + 8],  part[1]);
            atomicAdd(&s_sc[rbase + 16], part[2]);
            atomicAdd(&s_sc[rbase + 24], part[3]);
        }
        __syncthreads();
    }

    if (tid < 128) g_scores[m0 + tid] = s_sc[tid];
}

// ---------------- K3: softmax over S per batch ----------------
__global__ void softmax_kernel() {
    const int b = blockIdx.x;
    const int tid = threadIdx.x;
    const int lane = tid & 31, wid = tid >> 5;
    __shared__ float red[8];
    __shared__ float bcast;

    float vals[SEQ / 256];
#pragma unroll
    for (int i = 0; i < SEQ / 256; i++)
        vals[i] = g_scores[b * SEQ + i * 256 + tid];

    float m = vals[0];
#pragma unroll
    for (int i = 1; i < SEQ / 256; i++) m = fmaxf(m, vals[i]);
#pragma unroll
    for (int off = 16; off >= 1; off >>= 1)
        m = fmaxf(m, __shfl_xor_sync(0xffffffffu, m, off));
    if (lane == 0) red[wid] = m;
    __syncthreads();
    float bm = red[0];
#pragma unroll
    for (int w = 1; w < 8; w++) bm = fmaxf(bm, red[w]);
    __syncthreads();

    float sum = 0.f;
#pragma unroll
    for (int i = 0; i < SEQ / 256; i++) {
        vals[i] = __expf(vals[i] - bm);
        sum += vals[i];
    }
#pragma unroll
    for (int off = 16; off >= 1; off >>= 1)
        sum += __shfl_xor_sync(0xffffffffu, sum, off);
    if (lane == 0) red[wid] = sum;
    __syncthreads();
    if (tid == 0) {
        float t = 0.f;
#pragma unroll
        for (int w = 0; w < 8; w++) t += red[w];
        bcast = 1.0f / t;
    }
    __syncthreads();
    float inv = bcast;
#pragma unroll
    for (int i = 0; i < SEQ / 256; i++)
        g_attn[b * SEQ + i * 256 + tid] = vals[i] * inv;
}

// ---------------- K4a: context partials (split-S, NSC chunks) ----------------
__global__ void context_part_kernel(const float* __restrict__ enc) {
    const int b = blockIdx.z;
    const int sc = blockIdx.y;
    const int e = blockIdx.x * 128 + threadIdx.x;
    const int rows = SEQ / NSC;  // 128
    const float* A  = enc + (size_t)b * SEQ * EDIM + (size_t)sc * rows * EDIM;
    const float* at = g_attn + b * SEQ + sc * rows;
    float acc = 0.f;
#pragma unroll 8
    for (int s = 0; s < rows; s++)
        acc = fmaf(at[s], A[(size_t)s * EDIM + e], acc);
    g_ctx_part[((size_t)sc * BATCH + b) * EDIM + e] = acc;
}

// ---------------- K4b: sum partials ----------------
__global__ void context_sum_kernel(float* __restrict__ out) {
    const int i = blockIdx.x * 256 + threadIdx.x;
    float a = 0.f;
#pragma unroll
    for (int sc = 0; sc < NSC; sc++)
        a += g_ctx_part[(size_t)sc * BATCH * EDIM + i];
    out[i] = a;
}

// ---------------- launch ----------------
extern "C" void kernel_launch(void* const* d_in, const int* in_sizes, int n_in,
                              void* d_out, int out_size) {
    const float* enc = (const float*)d_in[0];
    const float* dec = (const float*)d_in[1];
    const float* w1  = (const float*)d_in[2];
    const float* b1  = (const float*)d_in[3];
    const float* w2  = (const float*)d_in[4];
    const float* b2  = (const float*)d_in[5];
    const float* v   = (const float*)d_in[6];
    // d_in[7] = bv: softmax-invariant, dropped
    float* out = (float*)d_out;

    cudaFuncSetAttribute(scores_mma_kernel,
                         cudaFuncAttributeMaxDynamicSharedMemorySize, SCORES_SMEM);

    conv_enc_kernel<<<(size_t)MROWS * EDIM / 2048, 256>>>(enc);
    conv_w1t_kernel<<<dim3(32, 32), dim3(32, 32)>>>(w1);
    qproj_kernel<<<dim3(BATCH, EDIM / 256), 256>>>(dec, w2, b2, b1);
    scores_mma_kernel<<<MROWS / 128, 256, SCORES_SMEM>>>(v);
    softmax_kernel<<<BATCH, 256>>>();
    context_part_kernel<<<dim3(EDIM / 128, NSC, BATCH), 128>>>(enc);
    context_sum_kernel<<<BATCH * EDIM / 256, 256>>>(out);
}